// round 1
// baseline (speedup 1.0000x reference)
#include <cuda_runtime.h>
#include <math.h>

// ---------------- problem constants ----------------
#define H_IMG 110
#define W_IMG 110
#define OHW   96
#define NBC   8                 // b*c = 2*4
#define EPSF  1e-8f
#define SPEC_U 1.4142135623730951e-3f   // sqrt(1e-6 + 1e-6)
#define TEMP_U 1.4142135623730951e-3f

// ---------------- pass 1: global thr reduction ----------------
#define RED_BLOCKS  128
#define RED_THREADS 256

__device__ double g_pcnt[RED_BLOCKS];
__device__ double g_psum[RED_BLOCKS];
__device__ double g_psum2[RED_BLOCKS];
__device__ float  g_thr;

// number of 15-wide windows (over a 96-long output axis) covering index i in [0,110)
__device__ __forceinline__ int wcount(int i) {
    int lo = i - 14; if (lo < 0) lo = 0;
    int hi = i;      if (hi > 95) hi = 95;
    return hi - lo + 1;
}

__global__ void reduce_kernel(const float* __restrict__ pf, int total) {
    __shared__ double sc[RED_THREADS], ss[RED_THREADS], ss2[RED_THREADS];
    double c = 0.0, s = 0.0, s2 = 0.0;
    for (int idx = blockIdx.x * blockDim.x + threadIdx.x; idx < total;
         idx += gridDim.x * blockDim.x) {
        float v = pf[idx];
        int w = idx % W_IMG;
        int h = (idx / W_IMG) % H_IMG;
        double mult = (double)(wcount(h) * wcount(w));
        if (v >= EPSF) {
            double dv = (double)v;
            c  += mult;
            s  += mult * dv;
            s2 += mult * dv * dv;
        }
    }
    int t = threadIdx.x;
    sc[t] = c; ss[t] = s; ss2[t] = s2;
    __syncthreads();
    for (int off = RED_THREADS / 2; off > 0; off >>= 1) {
        if (t < off) { sc[t] += sc[t+off]; ss[t] += ss[t+off]; ss2[t] += ss2[t+off]; }
        __syncthreads();
    }
    if (t == 0) {
        g_pcnt[blockIdx.x]  = sc[0];
        g_psum[blockIdx.x]  = ss[0];
        g_psum2[blockIdx.x] = ss2[0];
    }
}

__global__ void finalize_kernel() {
    if (threadIdx.x == 0 && blockIdx.x == 0) {
        double c = 0.0, s = 0.0, s2 = 0.0;
        for (int i = 0; i < RED_BLOCKS; i++) {   // fixed order -> deterministic
            c += g_pcnt[i]; s += g_psum[i]; s2 += g_psum2[i];
        }
        double m  = s  / c;
        double m2 = s2 / c;
        g_thr = (float)(2.0 * sqrt(m2 - m * m) / 5.0);
    }
}

// ---------------- pass 2: STARFM main kernel ----------------
#define TOX 32
#define TOY 8
#define SMW (TOX + 14)   // 46
#define SMH (TOY + 14)   // 22

__global__ __launch_bounds__(256)
void starfm_kernel(const float* __restrict__ pcg,
                   const float* __restrict__ pfg,
                   const float* __restrict__ pdg,
                   float* __restrict__ out)
{
    __shared__ float Spc[2][SMH][SMW];
    __shared__ float Spf[2][SMH][SMW];
    __shared__ float Spd[SMH][SMW];

    const int bc  = blockIdx.z;           // b*4 + c, matches (b,c,...) layout
    const int ty0 = blockIdx.y * TOY;
    const int tx0 = blockIdx.x * TOX;
    const int tid = threadIdx.y * 32 + threadIdx.x;

    const float* pc0 = pcg + (size_t)(bc * 2) * (H_IMG * W_IMG);
    const float* pc1 = pc0 + H_IMG * W_IMG;
    const float* pf0 = pfg + (size_t)(bc * 2) * (H_IMG * W_IMG);
    const float* pf1 = pf0 + H_IMG * W_IMG;
    const float* pd0 = pdg + (size_t)bc * (H_IMG * W_IMG);

    for (int i = tid; i < SMH * SMW; i += 256) {
        int r  = i / SMW;
        int cl = i - r * SMW;
        int g  = (ty0 + r) * W_IMG + (tx0 + cl);
        Spc[0][r][cl] = pc0[g];
        Spc[1][r][cl] = pc1[g];
        Spf[0][r][cl] = pf0[g];
        Spf[1][r][cl] = pf1[g];
        Spd[r][cl]    = pd0[g];
    }
    __syncthreads();

    const int tx = threadIdx.x, ty = threadIdx.y;
    const float thr = g_thr;

    // center-pixel values (MID = dy=7, dx=7)
    const float pcc0 = Spc[0][ty+7][tx+7], pcc1 = Spc[1][ty+7][tx+7];
    const float pfc0 = Spf[0][ty+7][tx+7], pfc1 = Spf[1][ty+7][tx+7];
    const float pdc  = Spd[ty+7][tx+7];
    const float maxspec = fmaxf(fabsf(pcc0 - pfc0), fabsf(pcc1 - pfc1)) + SPEC_U;
    const float maxtemp = fmaxf(fabsf(pcc0 - pdc),  fabsf(pcc1 - pdc))  + TEMP_U;

    float S0 = 0.0f, S1 = 0.0f;

    #pragma unroll
    for (int t = 0; t < 2; ++t) {
        const float pfc  = t ? pfc1 : pfc0;
        const bool  pfcv = (pfc >= EPSF);
        for (int dy = 0; dy < 15; ++dy) {
            const float* rpc = &Spc[t][ty + dy][tx];
            const float* rpf = &Spf[t][ty + dy][tx];
            const float* rpd = &Spd[ty + dy][tx];
            const int dy2 = (dy - 7) * (dy - 7);
            #pragma unroll
            for (int dx = 0; dx < 15; ++dx) {
                float pc = rpc[dx];
                float pf = rpf[dx];
                float pd = rpd[dx];
                float spec = fabsf(pc - pf);
                float temp = fabsf(pc - pd);
                bool pass = (spec < maxspec) & (temp < maxtemp) &
                            (pf >= EPSF) & pfcv & (fabsf(pf - pfc) < thr);
                if (pass) {
                    float spat = (float)(dy2 + (dx - 7) * (dx - 7)) * (1.0f / 7.0f) + 1.0f;
                    float den  = logf(spec + 1.0f) * logf(temp + 1.0f) * spat + EPSF;
                    float w    = 1.0f / den;
                    S0 += w;
                    S1 += w * ((pd + pf) - pc);
                }
            }
        }
    }

    const int oy = ty0 + ty, ox = tx0 + tx;
    out[((size_t)bc * OHW + oy) * OHW + ox] = S1 / (S0 + EPSF);
}

// ---------------- launch ----------------
extern "C" void kernel_launch(void* const* d_in, const int* in_sizes, int n_in,
                              void* d_out, int out_size)
{
    const float* pc = (const float*)d_in[0];   // prior_coarse (2,4,2,110,110)
    const float* pf = (const float*)d_in[1];   // prior_fine   (2,4,2,110,110)
    const float* pd = (const float*)d_in[2];   // pred_coarse  (2,4,110,110)
    float* out = (float*)d_out;                // (2,4,96,96)

    reduce_kernel<<<RED_BLOCKS, RED_THREADS>>>(pf, NBC * 2 * H_IMG * W_IMG);
    finalize_kernel<<<1, 32>>>();

    dim3 grid(OHW / TOX, OHW / TOY, NBC);      // (3, 12, 8)
    dim3 block(32, 8);
    starfm_kernel<<<grid, block>>>(pc, pf, pd, out);
}

// round 2
// speedup vs baseline: 1.5557x; 1.5557x over previous
#include <cuda_runtime.h>
#include <math.h>

// ---------------- problem constants ----------------
#define H_IMG 110
#define W_IMG 110
#define OHW   96
#define NBC   8                 // b*c = 2*4
#define EPSF  1e-8f
#define SPEC_U 1.4142135623730951e-3f   // sqrt(1e-6 + 1e-6)
#define TEMP_U 1.4142135623730951e-3f

// ---------------- pass 1: global thr reduction (fused finalize) --------------
#define RED_BLOCKS  128
#define RED_THREADS 256

__device__ double g_part[RED_BLOCKS][3];
__device__ unsigned int g_ticket = 0;
__device__ float  g_thr;

// number of 15-wide windows (over a 96-long output axis) covering index i
__device__ __forceinline__ int wcount(int i) {
    int lo = i - 14; if (lo < 0) lo = 0;
    int hi = i;      if (hi > 95) hi = 95;
    return hi - lo + 1;
}

__device__ __forceinline__ double warp_red(double v) {
    #pragma unroll
    for (int o = 16; o > 0; o >>= 1) v += __shfl_down_sync(0xffffffffu, v, o);
    return v;
}

__global__ void reduce_kernel(const float* __restrict__ pf) {
    const int total = NBC * 2 * H_IMG * W_IMG;
    double c = 0.0, s = 0.0, s2 = 0.0;
    for (int idx = blockIdx.x * blockDim.x + threadIdx.x; idx < total;
         idx += gridDim.x * blockDim.x) {
        float v = pf[idx];
        int w = idx % W_IMG;
        int h = (idx / W_IMG) % H_IMG;
        if (v >= EPSF) {
            double mult = (double)(wcount(h) * wcount(w));
            double dv = (double)v;
            c  += mult;
            s  += mult * dv;
            s2 += mult * dv * dv;
        }
    }
    __shared__ double sm[8][3];
    __shared__ int isLast;
    const int tid  = threadIdx.x;
    const int warp = tid >> 5, lane = tid & 31;

    c = warp_red(c); s = warp_red(s); s2 = warp_red(s2);
    if (lane == 0) { sm[warp][0] = c; sm[warp][1] = s; sm[warp][2] = s2; }
    __syncthreads();
    if (tid == 0) {
        double C = 0, S = 0, S2 = 0;
        #pragma unroll
        for (int w = 0; w < 8; w++) { C += sm[w][0]; S += sm[w][1]; S2 += sm[w][2]; }
        g_part[blockIdx.x][0] = C;
        g_part[blockIdx.x][1] = S;
        g_part[blockIdx.x][2] = S2;
        __threadfence();
        unsigned t = atomicAdd(&g_ticket, 1u);
        isLast = (t == RED_BLOCKS - 1);
    }
    __syncthreads();
    if (isLast) {
        __threadfence();
        double cc = 0, ss = 0, ss2 = 0;
        if (tid < RED_BLOCKS) {
            cc  = g_part[tid][0];
            ss  = g_part[tid][1];
            ss2 = g_part[tid][2];
        }
        cc = warp_red(cc); ss = warp_red(ss); ss2 = warp_red(ss2);
        if (lane == 0) { sm[warp][0] = cc; sm[warp][1] = ss; sm[warp][2] = ss2; }
        __syncthreads();
        if (tid == 0) {
            double C = 0, S = 0, S2 = 0;
            #pragma unroll
            for (int w = 0; w < 8; w++) { C += sm[w][0]; S += sm[w][1]; S2 += sm[w][2]; }
            double m  = S  / C;
            double m2 = S2 / C;
            g_thr = (float)(2.0 * sqrt(m2 - m * m) / 5.0);
            g_ticket = 0;   // reset for next graph replay
        }
    }
}

// ---------------- pass 2: STARFM main kernel ----------------
#define TOX 32
#define TOY 8
#define SMW (TOX + 14)   // 46
#define SMH (TOY + 14)   // 22

// log(fl(1+x))/2 via atanh form; rel err ~4e-7, matches reference arg rounding
__device__ __forceinline__ float log1p_half(float x) {
    float u   = 1.0f + x;        // same rounding as reference's (x + 1.0)
    float xp  = u - 1.0f;        // exact (u in [1,2])
    float up1 = u + 1.0f;
    float ri;
    asm("rcp.approx.f32 %0, %1;" : "=f"(ri) : "f"(up1));
    float z  = xp * ri;          // z in [0, 1/3]
    float z2 = z * z;
    float p  = fmaf(z2, 0.0909090909f, 0.1111111111f);  // 1/11, 1/9
    p = fmaf(p, z2, 0.1428571429f);                      // 1/7
    p = fmaf(p, z2, 0.2f);                               // 1/5
    p = fmaf(p, z2, 0.3333333333f);                      // 1/3
    p = fmaf(p, z2, 1.0f);
    return z * p;                // = atanh(z) = log(u)/2
}

__global__ __launch_bounds__(256, 2)
void starfm_kernel(const float* __restrict__ pcg,
                   const float* __restrict__ pfg,
                   const float* __restrict__ pdg,
                   float* __restrict__ out)
{
    __shared__ float Spc[2][SMH][SMW];
    __shared__ float Spf[2][SMH][SMW];
    __shared__ float Spd[SMH][SMW];

    const int bc  = blockIdx.z;
    const int ty0 = blockIdx.y * TOY;
    const int tx0 = blockIdx.x * TOX;
    const int tid = threadIdx.y * 32 + threadIdx.x;

    const float* pc0 = pcg + (size_t)(bc * 2) * (H_IMG * W_IMG);
    const float* pc1 = pc0 + H_IMG * W_IMG;
    const float* pf0 = pfg + (size_t)(bc * 2) * (H_IMG * W_IMG);
    const float* pf1 = pf0 + H_IMG * W_IMG;
    const float* pd0 = pdg + (size_t)bc * (H_IMG * W_IMG);

    for (int i = tid; i < SMH * SMW; i += 256) {
        int r  = i / SMW;
        int cl = i - r * SMW;
        int g  = (ty0 + r) * W_IMG + (tx0 + cl);
        Spc[0][r][cl] = pc0[g];
        Spc[1][r][cl] = pc1[g];
        Spf[0][r][cl] = pf0[g];
        Spf[1][r][cl] = pf1[g];
        Spd[r][cl]    = pd0[g];
    }
    __syncthreads();

    const int tx = threadIdx.x, ty = threadIdx.y;
    const float thr = g_thr;

    const float pcc0 = Spc[0][ty+7][tx+7], pcc1 = Spc[1][ty+7][tx+7];
    const float pfc0 = Spf[0][ty+7][tx+7], pfc1 = Spf[1][ty+7][tx+7];
    const float pdc  = Spd[ty+7][tx+7];
    const float maxspec = fmaxf(fabsf(pcc0 - pfc0), fabsf(pcc1 - pfc1)) + SPEC_U;
    const float maxtemp = fmaxf(fabsf(pcc0 - pdc),  fabsf(pcc1 - pdc))  + TEMP_U;

    float S0 = 0.0f, S1 = 0.0f;

    #pragma unroll
    for (int t = 0; t < 2; ++t) {
        const float pfc   = t ? pfc1 : pfc0;
        const float thr_t = (pfc >= EPSF) ? thr : -1.0f;  // folds center-valid
        #pragma unroll 1
        for (int dy = 0; dy < 15; ++dy) {
            const float dy2f = (float)((dy - 7) * (dy - 7));
            const float base = fmaf(dy2f, 4.0f / 7.0f, 4.0f);   // 4*(dy2/7 + 1)
            const float* rpc = &Spc[t][ty + dy][tx];
            const float* rpf = &Spf[t][ty + dy][tx];
            const float* rpd = &Spd[ty + dy][tx];
            #pragma unroll
            for (int dx = 0; dx < 15; ++dx) {
                const float cadd = (float)((dx - 7) * (dx - 7)) * (4.0f / 7.0f);
                float pc = rpc[dx];
                float pf = rpf[dx];
                float pd = rpd[dx];
                float spec = fabsf(pc - pf);
                float temp = fabsf(pc - pd);
                float l1 = log1p_half(spec);
                float l2 = log1p_half(temp);
                float spat4 = base + cadd;                      // = 4*spat
                float den = fmaf(l1 * l2, spat4, EPSF);         // = L1*L2*spat+eps
                float r;
                asm("rcp.approx.f32 %0, %1;" : "=f"(r) : "f"(den));
                int pass = (spec < maxspec) & (temp < maxtemp) &
                           (pf >= EPSF) & (fabsf(pf - pfc) < thr_t);
                float w = pass ? r : 0.0f;
                S0 += w;
                S1 = fmaf(w, (pd + pf) - pc, S1);
            }
        }
    }

    const int oy = ty0 + ty, ox = tx0 + tx;
    out[((size_t)bc * OHW + oy) * OHW + ox] = S1 / (S0 + EPSF);
}

// ---------------- launch ----------------
extern "C" void kernel_launch(void* const* d_in, const int* in_sizes, int n_in,
                              void* d_out, int out_size)
{
    const float* pc = (const float*)d_in[0];   // prior_coarse (2,4,2,110,110)
    const float* pf = (const float*)d_in[1];   // prior_fine   (2,4,2,110,110)
    const float* pd = (const float*)d_in[2];   // pred_coarse  (2,4,110,110)
    float* out = (float*)d_out;                // (2,4,96,96)

    reduce_kernel<<<RED_BLOCKS, RED_THREADS>>>(pf);

    dim3 grid(OHW / TOX, OHW / TOY, NBC);      // (3, 12, 8)
    dim3 block(32, 8);
    starfm_kernel<<<grid, block>>>(pc, pf, pd, out);
}

// round 4
// speedup vs baseline: 3.0441x; 1.9567x over previous
#include <cuda_runtime.h>
#include <math.h>

// ---------------- problem constants ----------------
#define H_IMG 110
#define W_IMG 110
#define NPIX  (H_IMG * W_IMG)      // 12100
#define OHW   96
#define NBC   8                    // b*c = 2*4
#define NPLANE (NBC * 2)           // 16 (bc, t)
#define EPSF  1e-8f
#define SPEC_U 1.4142135623730951e-3f
#define TEMP_U 1.4142135623730951e-3f

// ---------------- scratch (static: no allocation allowed) ----------------
__device__ float2 g_st[NPLANE * NPIX];   // (spec, temp)
__device__ float2 g_gv[NPLANE * NPIX];   // (G = log1p(spec)*log1p(temp), val = pd+pf-pc)
__device__ float  g_pfn[NPLANE * NPIX];  // pf if valid else NaN
__device__ float  g_thr;

#define PREP_BLOCKS  148
#define PREP_THREADS 256
__device__ double g_part[PREP_BLOCKS][3];
__device__ unsigned int g_ticket = 0;

__device__ __forceinline__ int wcount(int i) {   // #windows covering index i
    int lo = i - 14; if (lo < 0) lo = 0;
    int hi = i;      if (hi > 95) hi = 95;
    return hi - lo + 1;
}

__device__ __forceinline__ double warp_red(double v) {
    #pragma unroll
    for (int o = 16; o > 0; o >>= 1) v += __shfl_down_sync(0xffffffffu, v, o);
    return v;
}

// ---------------- pass 1: per-pixel precompute + fused thr reduction --------
__global__ __launch_bounds__(PREP_THREADS)
void prep_kernel(const float* __restrict__ pcg,
                 const float* __restrict__ pfg,
                 const float* __restrict__ pdg)
{
    double c = 0.0, s = 0.0, s2 = 0.0;
    const int total = NPLANE * NPIX;
    for (int idx = blockIdx.x * blockDim.x + threadIdx.x; idx < total;
         idx += gridDim.x * blockDim.x) {
        int p   = idx / NPIX;
        int pix = idx - p * NPIX;
        float vpc = pcg[idx];
        float vpf = pfg[idx];
        float vpd = pdg[(p >> 1) * NPIX + pix];

        float spec = fabsf(vpc - vpf);
        float temp = fabsf(vpc - vpd);
        float G    = logf(spec + 1.0f) * logf(temp + 1.0f);
        float val  = (vpd + vpf) - vpc;

        g_st[idx]  = make_float2(spec, temp);
        g_gv[idx]  = make_float2(G, val);
        g_pfn[idx] = (vpf >= EPSF) ? vpf : __int_as_float(0x7fffffff); // NaN

        if (vpf >= EPSF) {
            int h = pix / W_IMG, w = pix - h * W_IMG;
            double mult = (double)(wcount(h) * wcount(w));
            double dv = (double)vpf;
            c += mult; s += mult * dv; s2 += mult * dv * dv;
        }
    }

    __shared__ double sm[8][3];
    __shared__ int isLast;
    const int tid = threadIdx.x, warp = tid >> 5, lane = tid & 31;
    c = warp_red(c); s = warp_red(s); s2 = warp_red(s2);
    if (lane == 0) { sm[warp][0] = c; sm[warp][1] = s; sm[warp][2] = s2; }
    __syncthreads();
    if (tid == 0) {
        double C = 0, S = 0, S2 = 0;
        #pragma unroll
        for (int w = 0; w < 8; w++) { C += sm[w][0]; S += sm[w][1]; S2 += sm[w][2]; }
        g_part[blockIdx.x][0] = C; g_part[blockIdx.x][1] = S; g_part[blockIdx.x][2] = S2;
        __threadfence();
        unsigned t = atomicAdd(&g_ticket, 1u);
        isLast = (t == PREP_BLOCKS - 1);
    }
    __syncthreads();
    if (isLast) {
        __threadfence();
        double cc = 0, ss = 0, ss2 = 0;
        if (tid < PREP_BLOCKS) {
            cc = g_part[tid][0]; ss = g_part[tid][1]; ss2 = g_part[tid][2];
        }
        cc = warp_red(cc); ss = warp_red(ss); ss2 = warp_red(ss2);
        if (lane == 0) { sm[warp][0] = cc; sm[warp][1] = ss; sm[warp][2] = ss2; }
        __syncthreads();
        if (tid == 0) {
            double C = 0, S = 0, S2 = 0;
            #pragma unroll
            for (int w = 0; w < 8; w++) { C += sm[w][0]; S += sm[w][1]; S2 += sm[w][2]; }
            double m = S / C, m2 = S2 / C;
            g_thr = (float)(2.0 * sqrt(m2 - m * m) / 5.0);
            g_ticket = 0;     // reset for next graph replay
        }
    }
}

// ---------------- pass 2: STARFM main kernel ----------------
#define TOX 32
#define TOY 16            // tile 32x16 outputs; 256 threads x 2 outputs each
#define SMW (TOX + 14)    // 46
#define SMH (TOY + 14)    // 30

__device__ __forceinline__ void acc_one(float2 st, float2 gv, float pf,
                                        float spat, float ms, float mt,
                                        float pfc, float thr,
                                        float& S0, float& S1)
{
    float den = fmaf(gv.x, spat, EPSF);
    float w;
    asm("rcp.approx.f32 %0, %1;" : "=f"(w) : "f"(den));
    float d = pf - pfc;                                        // NaN-propagating
    int pass = (st.x < ms) & (st.y < mt) & (fabsf(d) < thr);   // NaN -> false
    w = pass ? w : 0.0f;
    S0 += w;
    S1 = fmaf(w, gv.y, S1);
}

__global__ __launch_bounds__(256, 2)
void starfm_kernel(float* __restrict__ out)
{
    __shared__ float2 Sst[SMH][SMW];
    __shared__ float2 Sgv[SMH][SMW];
    __shared__ float  Spf[SMH][SMW];

    const int bc  = blockIdx.z;
    const int ty0 = blockIdx.y * TOY;
    const int tx0 = blockIdx.x * TOX;
    const int tx  = threadIdx.x, ty = threadIdx.y;   // block (32, 8)
    const int tid = ty * 32 + tx;

    const float thr = g_thr;

    // center data for this thread's two outputs (rows 2*ty, 2*ty+1)
    float sp[2][2], tp[2][2], pfc[2][2];
    #pragma unroll
    for (int o = 0; o < 2; ++o)
        #pragma unroll
        for (int t = 0; t < 2; ++t) {
            int gi = (bc * 2 + t) * NPIX +
                     (ty0 + 2 * ty + o + 7) * W_IMG + (tx0 + tx + 7);
            float2 stc = g_st[gi];
            sp[o][t] = stc.x; tp[o][t] = stc.y;
            pfc[o][t] = g_pfn[gi];
        }
    const float ms0 = fmaxf(sp[0][0], sp[0][1]) + SPEC_U;
    const float mt0 = fmaxf(tp[0][0], tp[0][1]) + TEMP_U;
    const float ms1 = fmaxf(sp[1][0], sp[1][1]) + SPEC_U;
    const float mt1 = fmaxf(tp[1][0], tp[1][1]) + TEMP_U;

    float S0a = 0.f, S1a = 0.f, S0b = 0.f, S1b = 0.f;

    for (int t = 0; t < 2; ++t) {
        __syncthreads();    // protect prior-iteration tile before restage
        {
            const int pbase = (bc * 2 + t) * NPIX;
            for (int i = tid; i < SMH * SMW; i += 256) {
                int r  = i / SMW;
                int cl = i - r * SMW;
                int g  = pbase + (ty0 + r) * W_IMG + (tx0 + cl);
                Sst[r][cl] = g_st[g];
                Sgv[r][cl] = g_gv[g];
                Spf[r][cl] = g_pfn[g];
            }
        }
        __syncthreads();

        const float pfc0 = pfc[0][t];
        const float pfc1 = pfc[1][t];
        const int row0 = 2 * ty;

        // ---- r = 0: output 0 only (dy0 = 0 -> spat = 49/7 + 1 = 8) ----
        {
            const float2* rst = &Sst[row0][tx];
            const float2* rgv = &Sgv[row0][tx];
            const float*  rpf = &Spf[row0][tx];
            #pragma unroll
            for (int dx = 0; dx < 15; ++dx) {
                const float cadd = (float)((dx - 7) * (dx - 7)) * (1.0f / 7.0f);
                acc_one(rst[dx], rgv[dx], rpf[dx], 8.0f + cadd,
                        ms0, mt0, pfc0, thr, S0a, S1a);
            }
        }
        // ---- r = 1..14: both outputs (out0 dy=r, out1 dy=r-1) ----
        #pragma unroll 1
        for (int r = 1; r < 15; ++r) {
            int d0 = r - 7, d1 = r - 8;
            float base0 = fmaf((float)(d0 * d0), 1.0f / 7.0f, 1.0f);
            float base1 = fmaf((float)(d1 * d1), 1.0f / 7.0f, 1.0f);
            const float2* rst = &Sst[row0 + r][tx];
            const float2* rgv = &Sgv[row0 + r][tx];
            const float*  rpf = &Spf[row0 + r][tx];
            #pragma unroll
            for (int dx = 0; dx < 15; ++dx) {
                const float cadd = (float)((dx - 7) * (dx - 7)) * (1.0f / 7.0f);
                float2 st = rst[dx];
                float2 gv = rgv[dx];
                float  pf = rpf[dx];
                acc_one(st, gv, pf, base0 + cadd, ms0, mt0, pfc0, thr, S0a, S1a);
                acc_one(st, gv, pf, base1 + cadd, ms1, mt1, pfc1, thr, S0b, S1b);
            }
        }
        // ---- r = 15: output 1 only (dy1 = 14 -> spat = 8) ----
        {
            const float2* rst = &Sst[row0 + 15][tx];
            const float2* rgv = &Sgv[row0 + 15][tx];
            const float*  rpf = &Spf[row0 + 15][tx];
            #pragma unroll
            for (int dx = 0; dx < 15; ++dx) {
                const float cadd = (float)((dx - 7) * (dx - 7)) * (1.0f / 7.0f);
                acc_one(rst[dx], rgv[dx], rpf[dx], 8.0f + cadd,
                        ms1, mt1, pfc1, thr, S0b, S1b);
            }
        }
    }

    const int oy0 = ty0 + 2 * ty, ox = tx0 + tx;
    float* ob = out + (size_t)bc * OHW * OHW + ox;
    ob[(size_t)oy0 * OHW]       = S1a / (S0a + EPSF);
    ob[(size_t)(oy0 + 1) * OHW] = S1b / (S0b + EPSF);
}

// ---------------- launch ----------------
extern "C" void kernel_launch(void* const* d_in, const int* in_sizes, int n_in,
                              void* d_out, int out_size)
{
    const float* pc = (const float*)d_in[0];   // prior_coarse (2,4,2,110,110)
    const float* pf = (const float*)d_in[1];   // prior_fine   (2,4,2,110,110)
    const float* pd = (const float*)d_in[2];   // pred_coarse  (2,4,110,110)
    float* out = (float*)d_out;                // (2,4,96,96)

    prep_kernel<<<PREP_BLOCKS, PREP_THREADS>>>(pc, pf, pd);

    dim3 grid(OHW / TOX, OHW / TOY, NBC);      // (3, 6, 8) = 144 CTAs
    dim3 block(32, 8);
    starfm_kernel<<<grid, block>>>(out);
}

// round 5
// speedup vs baseline: 3.1128x; 1.0226x over previous
#include <cuda_runtime.h>
#include <math.h>

// ---------------- problem constants ----------------
#define H_IMG 110
#define W_IMG 110
#define NPIX  (H_IMG * W_IMG)      // 12100
#define OHW   96
#define NOUT  (OHW * OHW)          // 9216
#define NBC   8                    // b*c = 2*4
#define NPLANE (NBC * 2)           // 16 (bc, t)
#define EPSF  1e-8f
#define SPEC_U 1.4142135623730951e-3f
#define TEMP_U 1.4142135623730951e-3f

// ---------------- scratch (static: no allocation allowed) ----------------
__device__ float4 g_q[NPLANE * NPIX];    // (spec, temp, G, val)
__device__ float  g_pfn[NPLANE * NPIX];  // pf if valid else NaN
__device__ float  g_thr;
__device__ float2 g_ps[NPLANE][NOUT];    // per-(bc,t) partial (S0, S1)

#define PREP_BLOCKS  148
#define PREP_THREADS 256
__device__ double g_part[PREP_BLOCKS][3];
__device__ unsigned int g_ticket = 0;

__device__ __forceinline__ int wcount(int i) {   // #windows covering index i
    int lo = i - 14; if (lo < 0) lo = 0;
    int hi = i;      if (hi > 95) hi = 95;
    return hi - lo + 1;
}

__device__ __forceinline__ double warp_red(double v) {
    #pragma unroll
    for (int o = 16; o > 0; o >>= 1) v += __shfl_down_sync(0xffffffffu, v, o);
    return v;
}

// ---------------- pass 1: per-pixel precompute + fused thr reduction --------
__global__ __launch_bounds__(PREP_THREADS)
void prep_kernel(const float* __restrict__ pcg,
                 const float* __restrict__ pfg,
                 const float* __restrict__ pdg)
{
    double c = 0.0, s = 0.0, s2 = 0.0;
    const int total = NPLANE * NPIX;
    for (int idx = blockIdx.x * blockDim.x + threadIdx.x; idx < total;
         idx += gridDim.x * blockDim.x) {
        int p   = idx / NPIX;
        int pix = idx - p * NPIX;
        float vpc = pcg[idx];
        float vpf = pfg[idx];
        float vpd = pdg[(p >> 1) * NPIX + pix];

        float spec = fabsf(vpc - vpf);
        float temp = fabsf(vpc - vpd);
        float G    = logf(spec + 1.0f) * logf(temp + 1.0f);
        float val  = (vpd + vpf) - vpc;

        g_q[idx]   = make_float4(spec, temp, G, val);
        g_pfn[idx] = (vpf >= EPSF) ? vpf : __int_as_float(0x7fffffff); // NaN

        if (vpf >= EPSF) {
            int h = pix / W_IMG, w = pix - h * W_IMG;
            double mult = (double)(wcount(h) * wcount(w));
            double dv = (double)vpf;
            c += mult; s += mult * dv; s2 += mult * dv * dv;
        }
    }

    __shared__ double sm[8][3];
    __shared__ int isLast;
    const int tid = threadIdx.x, warp = tid >> 5, lane = tid & 31;
    c = warp_red(c); s = warp_red(s); s2 = warp_red(s2);
    if (lane == 0) { sm[warp][0] = c; sm[warp][1] = s; sm[warp][2] = s2; }
    __syncthreads();
    if (tid == 0) {
        double C = 0, S = 0, S2 = 0;
        #pragma unroll
        for (int w = 0; w < 8; w++) { C += sm[w][0]; S += sm[w][1]; S2 += sm[w][2]; }
        g_part[blockIdx.x][0] = C; g_part[blockIdx.x][1] = S; g_part[blockIdx.x][2] = S2;
        __threadfence();
        unsigned t = atomicAdd(&g_ticket, 1u);
        isLast = (t == PREP_BLOCKS - 1);
    }
    __syncthreads();
    if (isLast) {
        __threadfence();
        double cc = 0, ss = 0, ss2 = 0;
        if (tid < PREP_BLOCKS) {
            cc = g_part[tid][0]; ss = g_part[tid][1]; ss2 = g_part[tid][2];
        }
        cc = warp_red(cc); ss = warp_red(ss); ss2 = warp_red(ss2);
        if (lane == 0) { sm[warp][0] = cc; sm[warp][1] = ss; sm[warp][2] = ss2; }
        __syncthreads();
        if (tid == 0) {
            double C = 0, S = 0, S2 = 0;
            #pragma unroll
            for (int w = 0; w < 8; w++) { C += sm[w][0]; S += sm[w][1]; S2 += sm[w][2]; }
            double m = S / C, m2 = S2 / C;
            g_thr = (float)(2.0 * sqrt(m2 - m * m) / 5.0);
            g_ticket = 0;     // reset for next graph replay
        }
    }
}

// ---------------- pass 2: STARFM partial kernel (one (bc,t) plane per CTA) --
#define TOX 32
#define TOY 16            // tile 32x16 outputs; 256 threads x 2 outputs each
#define SMW (TOX + 14)    // 46
#define SMH (TOY + 14)    // 30

__device__ __forceinline__ void acc_one(float4 q, float pf,
                                        float spat, float ms, float mt,
                                        float pfc, float thr,
                                        float& S0, float& S1)
{
    float den = fmaf(q.z, spat, EPSF);
    float w;
    asm("rcp.approx.f32 %0, %1;" : "=f"(w) : "f"(den));
    float d = pf - pfc;                                        // NaN-propagating
    int pass = (q.x < ms) & (q.y < mt) & (fabsf(d) < thr);     // NaN -> false
    w = pass ? w : 0.0f;
    S0 += w;
    S1 = fmaf(w, q.w, S1);
}

__global__ __launch_bounds__(256, 2)
void starfm_kernel()
{
    __shared__ float4 Sq[SMH][SMW];
    __shared__ float  Spf[SMH][SMW];

    const int pz  = blockIdx.z;           // plane = bc*2 + t
    const int bc  = pz >> 1;
    const int ty0 = blockIdx.y * TOY;
    const int tx0 = blockIdx.x * TOX;
    const int tx  = threadIdx.x, ty = threadIdx.y;   // block (32, 8)
    const int tid = ty * 32 + tx;

    const float thr = g_thr;

    // stage this plane's tile
    {
        const int pbase = pz * NPIX;
        for (int i = tid; i < SMH * SMW; i += 256) {
            int r  = i / SMW;
            int cl = i - r * SMW;
            int g  = pbase + (ty0 + r) * W_IMG + (tx0 + cl);
            Sq[r][cl]  = g_q[g];
            Spf[r][cl] = g_pfn[g];
        }
    }

    // center data: ms/mt need max over BOTH t planes; pfc is own-t only
    float ms[2], mt[2], pfc[2];
    #pragma unroll
    for (int o = 0; o < 2; ++o) {
        int cpix = (ty0 + 2 * ty + o + 7) * W_IMG + (tx0 + tx + 7);
        float4 q0 = g_q[(bc * 2 + 0) * NPIX + cpix];
        float4 q1 = g_q[(bc * 2 + 1) * NPIX + cpix];
        ms[o]  = fmaxf(q0.x, q1.x) + SPEC_U;
        mt[o]  = fmaxf(q0.y, q1.y) + TEMP_U;
        pfc[o] = g_pfn[pz * NPIX + cpix];
    }
    __syncthreads();

    float S0a = 0.f, S1a = 0.f, S0b = 0.f, S1b = 0.f;
    const int row0 = 2 * ty;

    // ---- r = 0: output 0 only (dy0 = 0 -> spat = 49/7 + 1 = 8) ----
    {
        const float4* rq  = &Sq[row0][tx];
        const float*  rpf = &Spf[row0][tx];
        #pragma unroll
        for (int dx = 0; dx < 15; ++dx) {
            const float cadd = (float)((dx - 7) * (dx - 7)) * (1.0f / 7.0f);
            acc_one(rq[dx], rpf[dx], 8.0f + cadd, ms[0], mt[0], pfc[0], thr, S0a, S1a);
        }
    }
    // ---- r = 1..14: both outputs (out0 dy=r, out1 dy=r-1) ----
    #pragma unroll 1
    for (int r = 1; r < 15; ++r) {
        int d0 = r - 7, d1 = r - 8;
        float base0 = fmaf((float)(d0 * d0), 1.0f / 7.0f, 1.0f);
        float base1 = fmaf((float)(d1 * d1), 1.0f / 7.0f, 1.0f);
        const float4* rq  = &Sq[row0 + r][tx];
        const float*  rpf = &Spf[row0 + r][tx];
        #pragma unroll
        for (int dx = 0; dx < 15; ++dx) {
            const float cadd = (float)((dx - 7) * (dx - 7)) * (1.0f / 7.0f);
            float4 q = rq[dx];
            float pf = rpf[dx];
            acc_one(q, pf, base0 + cadd, ms[0], mt[0], pfc[0], thr, S0a, S1a);
            acc_one(q, pf, base1 + cadd, ms[1], mt[1], pfc[1], thr, S0b, S1b);
        }
    }
    // ---- r = 15: output 1 only (dy1 = 14 -> spat = 8) ----
    {
        const float4* rq  = &Sq[row0 + 15][tx];
        const float*  rpf = &Spf[row0 + 15][tx];
        #pragma unroll
        for (int dx = 0; dx < 15; ++dx) {
            const float cadd = (float)((dx - 7) * (dx - 7)) * (1.0f / 7.0f);
            acc_one(rq[dx], rpf[dx], 8.0f + cadd, ms[1], mt[1], pfc[1], thr, S0b, S1b);
        }
    }

    const int oy0 = ty0 + 2 * ty, ox = tx0 + tx;
    g_ps[pz][(oy0 + 0) * OHW + ox] = make_float2(S0a, S1a);
    g_ps[pz][(oy0 + 1) * OHW + ox] = make_float2(S0b, S1b);
}

// ---------------- pass 3: combine t-partials ----------------
__global__ __launch_bounds__(256)
void combine_kernel(float* __restrict__ out)
{
    int i = blockIdx.x * blockDim.x + threadIdx.x;    // 0 .. NBC*NOUT-1
    if (i >= NBC * NOUT) return;
    int bc  = i / NOUT;
    int pix = i - bc * NOUT;
    float2 a = g_ps[bc * 2 + 0][pix];
    float2 b = g_ps[bc * 2 + 1][pix];
    out[i] = (a.y + b.y) / ((a.x + b.x) + EPSF);
}

// ---------------- launch ----------------
extern "C" void kernel_launch(void* const* d_in, const int* in_sizes, int n_in,
                              void* d_out, int out_size)
{
    const float* pc = (const float*)d_in[0];   // prior_coarse (2,4,2,110,110)
    const float* pf = (const float*)d_in[1];   // prior_fine   (2,4,2,110,110)
    const float* pd = (const float*)d_in[2];   // pred_coarse  (2,4,110,110)
    float* out = (float*)d_out;                // (2,4,96,96)

    prep_kernel<<<PREP_BLOCKS, PREP_THREADS>>>(pc, pf, pd);

    dim3 grid(OHW / TOX, OHW / TOY, NPLANE);   // (3, 6, 16) = 288 CTAs
    dim3 block(32, 8);
    starfm_kernel<<<grid, block>>>();

    combine_kernel<<<(NBC * NOUT + 255) / 256, 256>>>(out);
}